// round 8
// baseline (speedup 1.0000x reference)
#include <cuda_runtime.h>

// ============================================================================
// Compile-time real Wigner-3j coefficients.
// All math in constexpr double; values baked into SASS as FFMA immediates.
// ============================================================================

__host__ __device__ constexpr double cfact(int n) {
  double r = 1.0;
  for (int i = 2; i <= n; ++i) r *= (double)i;
  return r;
}

__host__ __device__ constexpr double csqrt_(double x) {
  if (x <= 0.0) return 0.0;
  double g = x > 1.0 ? x : 1.0;
  for (int i = 0; i < 80; ++i) g = 0.5 * (g + x / g);
  return g;
}

struct CD { double re, im; };
__host__ __device__ constexpr CD cmul_(CD a, CD b) {
  return CD{ a.re*b.re - a.im*b.im, a.re*b.im + a.im*b.re };
}

struct QCol { int cnt; int m[2]; CD v[2]; };

__host__ __device__ constexpr QCol qcol(int l, int c) {
  QCol q{};
  const double is2 = 0.70710678118654752440;
  int mu = c - l;
  if (mu == 0) {
    q.cnt = 1; q.m[0] = 0; q.v[0] = CD{1.0, 0.0};
  } else if (mu > 0) {
    q.cnt = 2;
    q.m[0] = -mu; q.v[0] = CD{is2, 0.0};
    q.m[1] =  mu; q.v[1] = CD{(mu & 1) ? -is2 : is2, 0.0};
  } else {
    int am = -mu;
    q.cnt = 2;
    q.m[0] = -am; q.v[0] = CD{0.0, -is2};
    q.m[1] =  am; q.v[1] = CD{0.0, (am & 1) ? -is2 : is2};
  }
  CD ph{1.0, 0.0};
  switch (l & 3) {
    case 0: ph = CD{ 1.0,  0.0}; break;
    case 1: ph = CD{ 0.0, -1.0}; break;
    case 2: ph = CD{-1.0,  0.0}; break;
    default: ph = CD{ 0.0,  1.0}; break;
  }
  for (int t = 0; t < q.cnt; ++t) q.v[t] = cmul_(q.v[t], ph);
  return q;
}

__host__ __device__ constexpr double cgc(int j1, int m1, int j2, int m2, int j3, int m3) {
  if (m1 + m2 != m3) return 0.0;
  int vmin = -j1 + j2 + m3;
  if (-j1 + m1 > vmin) vmin = -j1 + m1;
  if (vmin < 0) vmin = 0;
  int vmax = j2 + j3 + m1;
  if (j3 - j1 + j2 < vmax) vmax = j3 - j1 + j2;
  if (j3 + m3 < vmax)      vmax = j3 + m3;
  if (vmax < vmin) return 0.0;
  double C = csqrt_((2.0*j3 + 1.0) * cfact(j3+j1-j2) * cfact(j3-j1+j2) * cfact(j1+j2-j3)
                    * cfact(j3+m3) * cfact(j3-m3)
                    / (cfact(j1+j2+j3+1) * cfact(j1-m1) * cfact(j1+m1)
                       * cfact(j2-m2) * cfact(j2+m2)));
  double S = 0.0;
  for (int v = vmin; v <= vmax; ++v) {
    double t = cfact(j2+j3+m1-v) * cfact(j1-m1+v)
             / (cfact(v) * cfact(j3-j1+j2-v) * cfact(j3+m3-v) * cfact(j1-j2-m3+v));
    S += ((v + j2 + m2) & 1) ? -t : t;
  }
  return C * S;
}

__host__ __device__ constexpr double w3j_raw(int l1, int l2, int l3, int i, int j, int k) {
  QCol q1 = qcol(l1, i), q2 = qcol(l2, j), q3 = qcol(l3, k);
  CD acc{0.0, 0.0};
  for (int x = 0; x < q1.cnt; ++x)
    for (int y = 0; y < q2.cnt; ++y)
      for (int z = 0; z < q3.cnt; ++z) {
        double cg = cgc(l1, q1.m[x], l2, q2.m[y], l3, q3.m[z]);
        if (cg != 0.0) {
          CD t = cmul_(cmul_(q1.v[x], q2.v[y]), q3.v[z]);
          acc.re += t.re * cg;
          acc.im += t.im * cg;
        }
      }
  return acc.re;
}

__host__ __device__ constexpr double w3j_norm(int l1, int l2, int l3) {
  double s = 0.0;
  int n1 = 2*l1 + 1, n2 = 2*l2 + 1, n3 = 2*l3 + 1;
  for (int i = 0; i < n1; ++i)
    for (int j = 0; j < n2; ++j)
      for (int k = 0; k < n3; ++k) {
        double v = w3j_raw(l1, l2, l3, i, j, k);
        s += v * v;
      }
  return csqrt_(s);
}

// ============================================================================
// Pair-grouped contraction (l1<=l2): each symmetrized product p(i,j) computed
// once and contracted into every admissible l3. Coefficients fold to FFMA
// immediates. Even parity => w3j(l2,l1,l3)[j,i,k]==w3j(l1,l2,l3)[i,j,k].
// ============================================================================
#define NPAIR 10
struct Pair { int l1, l2; };
constexpr Pair PRS[NPAIR] = {
  {0,0},{0,1},{0,2},{0,3},{1,1},{1,2},{1,3},{2,2},{2,3},{3,3}
};

__host__ __device__ constexpr int l3start(int l1, int l2) {
  int s = l1 + l2;
  while (s > 4) s -= 2;
  return s;
}

template <int P, int I, int J, int L3, int K>
__device__ __forceinline__ void kstep(float p, float (&acc)[25]) {
  constexpr int l1 = PRS[P].l1, l2 = PRS[P].l2;
  constexpr int n3 = 2*L3 + 1, o3 = L3*L3;
  if constexpr (K < n3) {
    constexpr double wr = w3j_raw(l1, l2, L3, I, J, K);
    if constexpr (wr > 1e-12 || wr < -1e-12) {
      constexpr float w = (float)(wr / w3j_norm(l1, l2, L3));
      acc[o3 + K] = fmaf(p, w, acc[o3 + K]);
    }
    kstep<P, I, J, L3, K + 1>(p, acc);
  }
}

template <int P, int I, int J, int L3>
__device__ __forceinline__ void l3step(float p, float (&acc)[25]) {
  constexpr int l1 = PRS[P].l1, l2 = PRS[P].l2;
  constexpr int lmin = (l1 > l2) ? (l1 - l2) : (l2 - l1);
  if constexpr (L3 >= lmin) {
    kstep<P, I, J, L3, 0>(p, acc);
    if constexpr (L3 - 2 >= 0) l3step<P, I, J, L3 - 2>(p, acc);
  }
}

template <int P, int I, int J>
__device__ __forceinline__ void jstep(const float (&a)[16], const float (&b)[16],
                                      float (&acc)[25]) {
  constexpr int l1 = PRS[P].l1, l2 = PRS[P].l2;
  constexpr int n2 = 2*l2 + 1, o1 = l1*l1, o2 = l2*l2;
  if constexpr (J < n2) {
    if constexpr (!(l1 == l2 && J < I)) {
      float p;
      if constexpr (l1 == l2) {
        if constexpr (J == I) p = a[o1 + I] * b[o2 + I];
        else                  p = a[o1 + I] * b[o2 + J] + a[o1 + J] * b[o2 + I];
      } else {
        p = a[o1 + I] * b[o2 + J] + a[o2 + J] * b[o1 + I];
      }
      l3step<P, I, J, l3start(l1, l2)>(p, acc);
    }
    jstep<P, I, J + 1>(a, b, acc);
  }
}

template <int P, int I>
__device__ __forceinline__ void istep(const float (&a)[16], const float (&b)[16],
                                      float (&acc)[25]) {
  constexpr int n1 = 2*PRS[P].l1 + 1;
  if constexpr (I < n1) {
    jstep<P, I, 0>(a, b, acc);
    istep<P, I + 1>(a, b, acc);
  }
}

template <int P>
__device__ __forceinline__ void contract_from(const float (&a)[16], const float (&b)[16],
                                              float (&acc)[25]) {
  if constexpr (P < NPAIR) {
    istep<P, 0>(a, b, acc);
    contract_from<P + 1>(a, b, acc);
  }
}

// Load one item's 16-float irrep vector as 4 float4s.
__device__ __forceinline__ void load16(const float* __restrict__ P, int item,
                                       float (&r)[16]) {
  const float4* p4 = reinterpret_cast<const float4*>(P) + (size_t)item * 4;
  float4 v;
  v = p4[0]; r[ 0]=v.x; r[ 1]=v.y; r[ 2]=v.z; r[ 3]=v.w;
  v = p4[1]; r[ 4]=v.x; r[ 5]=v.y; r[ 6]=v.z; r[ 7]=v.w;
  v = p4[2]; r[ 8]=v.x; r[ 9]=v.y; r[10]=v.z; r[11]=v.w;
  v = p4[3]; r[12]=v.x; r[13]=v.y; r[14]=v.z; r[15]=v.w;
}

// ============================================================================
// Main kernel. One thread per (node,channel) item. Per-warp smem staging
// drained with __syncwarp only — no block-wide barriers in the main loop.
// __launch_bounds__(256, 4): pin regs <= 64 so 4 CTAs fit per SM.
// ============================================================================
__global__ __launch_bounds__(256, 4)
void tp_kernel(const float* __restrict__ A, const float* __restrict__ B,
               float* __restrict__ O, int nitems) {
  __shared__ float sstage[8 * 800];   // 8 warps x (32 items x 25 outputs)

  const int warp = threadIdx.x >> 5;
  const int lane = threadIdx.x & 31;
  float* swarp = sstage + warp * 800;
  const float4* sw4 = reinterpret_cast<const float4*>(swarp);

  for (int base = blockIdx.x * 256; base < nitems; base += gridDim.x * 256) {
    const int wbase = base + warp * 32;       // first item of this warp's group
    const int item  = wbase + lane;
    const bool valid = item < nitems;
    float a[16], b[16], acc[25];

    if (valid) {
      load16(A, item, a);
      load16(B, item, b);
      #pragma unroll
      for (int k = 0; k < 25; ++k) acc[k] = 0.f;
      contract_from<0>(a, b, acc);
    }

    __syncwarp();   // previous group's staging reads are done
    if (valid) {
      #pragma unroll
      for (int k = 0; k < 25; ++k) swarp[lane * 25 + k] = acc[k];
    }
    __syncwarp();

    int vcnt = nitems - wbase;                 // items this warp group covers
    if (vcnt >= 32) {
      // 32 items * 25 floats = 800 floats = 200 float4, coalesced.
      float4* ov = reinterpret_cast<float4*>(O + (size_t)wbase * 25);
      #pragma unroll
      for (int r = 0; r < 6; ++r) ov[r * 32 + lane] = sw4[r * 32 + lane];
      if (lane < 8) ov[192 + lane] = sw4[192 + lane];
    } else if (vcnt > 0) {
      int cnt = vcnt * 25;
      float* op = O + (size_t)wbase * 25;
      for (int r = lane; r < cnt; r += 32) op[r] = swarp[r];
    }
  }
}

// ============================================================================
// Launch: persistent single wave, 4 resident CTAs per SM (148 x 4 = 592).
// ============================================================================
extern "C" void kernel_launch(void* const* d_in, const int* in_sizes, int n_in,
                              void* d_out, int out_size) {
  const float* A = (const float*)d_in[0];
  const float* B = (const float*)d_in[1];
  float* O = (float*)d_out;
  int nitems = in_sizes[0] / 16;
  if (nitems <= 0) return;

  int chunks = (nitems + 255) / 256;
  int grid = chunks < 592 ? chunks : 592;
  tp_kernel<<<grid, 256>>>(A, B, O, nitems);
}

// round 9
// speedup vs baseline: 1.1821x; 1.1821x over previous
#include <cuda_runtime.h>

// ============================================================================
// Compile-time real Wigner-3j coefficients.
// All math in constexpr double; values baked into SASS as FFMA immediates.
// ============================================================================

__host__ __device__ constexpr double cfact(int n) {
  double r = 1.0;
  for (int i = 2; i <= n; ++i) r *= (double)i;
  return r;
}

__host__ __device__ constexpr double csqrt_(double x) {
  if (x <= 0.0) return 0.0;
  double g = x > 1.0 ? x : 1.0;
  for (int i = 0; i < 80; ++i) g = 0.5 * (g + x / g);
  return g;
}

struct CD { double re, im; };
__host__ __device__ constexpr CD cmul_(CD a, CD b) {
  return CD{ a.re*b.re - a.im*b.im, a.re*b.im + a.im*b.re };
}

struct QCol { int cnt; int m[2]; CD v[2]; };

__host__ __device__ constexpr QCol qcol(int l, int c) {
  QCol q{};
  const double is2 = 0.70710678118654752440;
  int mu = c - l;
  if (mu == 0) {
    q.cnt = 1; q.m[0] = 0; q.v[0] = CD{1.0, 0.0};
  } else if (mu > 0) {
    q.cnt = 2;
    q.m[0] = -mu; q.v[0] = CD{is2, 0.0};
    q.m[1] =  mu; q.v[1] = CD{(mu & 1) ? -is2 : is2, 0.0};
  } else {
    int am = -mu;
    q.cnt = 2;
    q.m[0] = -am; q.v[0] = CD{0.0, -is2};
    q.m[1] =  am; q.v[1] = CD{0.0, (am & 1) ? -is2 : is2};
  }
  CD ph{1.0, 0.0};
  switch (l & 3) {
    case 0: ph = CD{ 1.0,  0.0}; break;
    case 1: ph = CD{ 0.0, -1.0}; break;
    case 2: ph = CD{-1.0,  0.0}; break;
    default: ph = CD{ 0.0,  1.0}; break;
  }
  for (int t = 0; t < q.cnt; ++t) q.v[t] = cmul_(q.v[t], ph);
  return q;
}

__host__ __device__ constexpr double cgc(int j1, int m1, int j2, int m2, int j3, int m3) {
  if (m1 + m2 != m3) return 0.0;
  int vmin = -j1 + j2 + m3;
  if (-j1 + m1 > vmin) vmin = -j1 + m1;
  if (vmin < 0) vmin = 0;
  int vmax = j2 + j3 + m1;
  if (j3 - j1 + j2 < vmax) vmax = j3 - j1 + j2;
  if (j3 + m3 < vmax)      vmax = j3 + m3;
  if (vmax < vmin) return 0.0;
  double C = csqrt_((2.0*j3 + 1.0) * cfact(j3+j1-j2) * cfact(j3-j1+j2) * cfact(j1+j2-j3)
                    * cfact(j3+m3) * cfact(j3-m3)
                    / (cfact(j1+j2+j3+1) * cfact(j1-m1) * cfact(j1+m1)
                       * cfact(j2-m2) * cfact(j2+m2)));
  double S = 0.0;
  for (int v = vmin; v <= vmax; ++v) {
    double t = cfact(j2+j3+m1-v) * cfact(j1-m1+v)
             / (cfact(v) * cfact(j3-j1+j2-v) * cfact(j3+m3-v) * cfact(j1-j2-m3+v));
    S += ((v + j2 + m2) & 1) ? -t : t;
  }
  return C * S;
}

__host__ __device__ constexpr double w3j_raw(int l1, int l2, int l3, int i, int j, int k) {
  QCol q1 = qcol(l1, i), q2 = qcol(l2, j), q3 = qcol(l3, k);
  CD acc{0.0, 0.0};
  for (int x = 0; x < q1.cnt; ++x)
    for (int y = 0; y < q2.cnt; ++y)
      for (int z = 0; z < q3.cnt; ++z) {
        double cg = cgc(l1, q1.m[x], l2, q2.m[y], l3, q3.m[z]);
        if (cg != 0.0) {
          CD t = cmul_(cmul_(q1.v[x], q2.v[y]), q3.v[z]);
          acc.re += t.re * cg;
          acc.im += t.im * cg;
        }
      }
  return acc.re;
}

__host__ __device__ constexpr double w3j_norm(int l1, int l2, int l3) {
  double s = 0.0;
  int n1 = 2*l1 + 1, n2 = 2*l2 + 1, n3 = 2*l3 + 1;
  for (int i = 0; i < n1; ++i)
    for (int j = 0; j < n2; ++j)
      for (int k = 0; k < n3; ++k) {
        double v = w3j_raw(l1, l2, l3, i, j, k);
        s += v * v;
      }
  return csqrt_(s);
}

// ============================================================================
// Pair-grouped contraction (l1<=l2): each symmetrized product p(i,j) computed
// once and contracted into every admissible l3. Coefficients fold to FFMA
// immediates. Even parity => w3j(l2,l1,l3)[j,i,k]==w3j(l1,l2,l3)[i,j,k].
// ============================================================================
#define NPAIR 10
struct Pair { int l1, l2; };
constexpr Pair PRS[NPAIR] = {
  {0,0},{0,1},{0,2},{0,3},{1,1},{1,2},{1,3},{2,2},{2,3},{3,3}
};

__host__ __device__ constexpr int l3start(int l1, int l2) {
  int s = l1 + l2;
  while (s > 4) s -= 2;
  return s;
}

template <int P, int I, int J, int L3, int K>
__device__ __forceinline__ void kstep(float p, float (&acc)[25]) {
  constexpr int l1 = PRS[P].l1, l2 = PRS[P].l2;
  constexpr int n3 = 2*L3 + 1, o3 = L3*L3;
  if constexpr (K < n3) {
    constexpr double wr = w3j_raw(l1, l2, L3, I, J, K);
    if constexpr (wr > 1e-12 || wr < -1e-12) {
      constexpr float w = (float)(wr / w3j_norm(l1, l2, L3));
      acc[o3 + K] = fmaf(p, w, acc[o3 + K]);
    }
    kstep<P, I, J, L3, K + 1>(p, acc);
  }
}

template <int P, int I, int J, int L3>
__device__ __forceinline__ void l3step(float p, float (&acc)[25]) {
  constexpr int l1 = PRS[P].l1, l2 = PRS[P].l2;
  constexpr int lmin = (l1 > l2) ? (l1 - l2) : (l2 - l1);
  if constexpr (L3 >= lmin) {
    kstep<P, I, J, L3, 0>(p, acc);
    if constexpr (L3 - 2 >= 0) l3step<P, I, J, L3 - 2>(p, acc);
  }
}

template <int P, int I, int J>
__device__ __forceinline__ void jstep(const float (&a)[16], const float (&b)[16],
                                      float (&acc)[25]) {
  constexpr int l1 = PRS[P].l1, l2 = PRS[P].l2;
  constexpr int n2 = 2*l2 + 1, o1 = l1*l1, o2 = l2*l2;
  if constexpr (J < n2) {
    if constexpr (!(l1 == l2 && J < I)) {
      float p;
      if constexpr (l1 == l2) {
        if constexpr (J == I) p = a[o1 + I] * b[o2 + I];
        else                  p = a[o1 + I] * b[o2 + J] + a[o1 + J] * b[o2 + I];
      } else {
        p = a[o1 + I] * b[o2 + J] + a[o2 + J] * b[o1 + I];
      }
      l3step<P, I, J, l3start(l1, l2)>(p, acc);
    }
    jstep<P, I, J + 1>(a, b, acc);
  }
}

template <int P, int I>
__device__ __forceinline__ void istep(const float (&a)[16], const float (&b)[16],
                                      float (&acc)[25]) {
  constexpr int n1 = 2*PRS[P].l1 + 1;
  if constexpr (I < n1) {
    jstep<P, I, 0>(a, b, acc);
    istep<P, I + 1>(a, b, acc);
  }
}

template <int P>
__device__ __forceinline__ void contract_from(const float (&a)[16], const float (&b)[16],
                                              float (&acc)[25]) {
  if constexpr (P < NPAIR) {
    istep<P, 0>(a, b, acc);
    contract_from<P + 1>(a, b, acc);
  }
}

// Load one item's 16-float irrep vector as 4 float4s.
__device__ __forceinline__ void load16(const float* __restrict__ P, int item,
                                       float (&r)[16]) {
  const float4* p4 = reinterpret_cast<const float4*>(P) + (size_t)item * 4;
  float4 v;
  v = p4[0]; r[ 0]=v.x; r[ 1]=v.y; r[ 2]=v.z; r[ 3]=v.w;
  v = p4[1]; r[ 4]=v.x; r[ 5]=v.y; r[ 6]=v.z; r[ 7]=v.w;
  v = p4[2]; r[ 8]=v.x; r[ 9]=v.y; r[10]=v.z; r[11]=v.w;
  v = p4[3]; r[12]=v.x; r[13]=v.y; r[14]=v.z; r[15]=v.w;
}

// ============================================================================
// Main kernel. TWO items per thread (item, item+32): amortizes per-iteration
// overhead (loads front-batched for 2x MLP, staging drain, loop control) over
// twice the work. Per-warp smem staging (64 items x 25 floats) drained with
// __syncwarp only — no block-wide barriers in the main loop.
// ============================================================================
__global__ __launch_bounds__(256, 2)
void tp_kernel(const float* __restrict__ A, const float* __restrict__ B,
               float* __restrict__ O, int nitems) {
  __shared__ float sstage[8 * 1600];   // 8 warps x (64 items x 25 outputs)

  const int warp = threadIdx.x >> 5;
  const int lane = threadIdx.x & 31;
  float* swarp = sstage + warp * 1600;
  const float4* sw4 = reinterpret_cast<const float4*>(swarp);

  const int stride = gridDim.x * 512;
  for (int base = blockIdx.x * 512; base < nitems; base += stride) {
    const int wbase = base + warp * 64;        // first item of this warp's group
    const int it0 = wbase + lane;
    const int it1 = it0 + 32;
    const int c0 = it0 < nitems ? it0 : nitems - 1;   // clamped (stores guarded)
    const int c1 = it1 < nitems ? it1 : nitems - 1;

    // Front-batch all 16 vector loads (64 sectors in flight per warp).
    float a0[16], b0[16], a1[16], b1[16];
    load16(A, c0, a0);
    load16(B, c0, b0);
    load16(A, c1, a1);
    load16(B, c1, b1);

    float acc0[25], acc1[25];
    #pragma unroll
    for (int k = 0; k < 25; ++k) { acc0[k] = 0.f; acc1[k] = 0.f; }
    contract_from<0>(a0, b0, acc0);
    contract_from<0>(a1, b1, acc1);

    __syncwarp();   // previous group's staging reads are done
    if (it0 < nitems) {
      #pragma unroll
      for (int k = 0; k < 25; ++k) swarp[lane * 25 + k] = acc0[k];
    }
    if (it1 < nitems) {
      #pragma unroll
      for (int k = 0; k < 25; ++k) swarp[(lane + 32) * 25 + k] = acc1[k];
    }
    __syncwarp();

    int vcnt = nitems - wbase;                 // items this warp group covers
    if (vcnt >= 64) {
      // 64 items * 25 floats = 1600 floats = 400 float4, coalesced.
      float4* ov = reinterpret_cast<float4*>(O + (size_t)wbase * 25);
      #pragma unroll
      for (int r = 0; r < 12; ++r) ov[r * 32 + lane] = sw4[r * 32 + lane];
      if (lane < 16) ov[384 + lane] = sw4[384 + lane];
    } else if (vcnt > 0) {
      int cnt = vcnt * 25;
      float* op = O + (size_t)wbase * 25;
      for (int r = lane; r < cnt; r += 32) op[r] = swarp[r];
    }
  }
}

// ============================================================================
// Launch: persistent single wave, 2 resident CTAs per SM (148 x 2 = 296).
// ============================================================================
extern "C" void kernel_launch(void* const* d_in, const int* in_sizes, int n_in,
                              void* d_out, int out_size) {
  const float* A = (const float*)d_in[0];
  const float* B = (const float*)d_in[1];
  float* O = (float*)d_out;
  int nitems = in_sizes[0] / 16;
  if (nitems <= 0) return;

  int chunks = (nitems + 511) / 512;
  int grid = chunks < 296 ? chunks : 296;
  tp_kernel<<<grid, 256>>>(A, B, O, nitems);
}